// round 1
// baseline (speedup 1.0000x reference)
#include <cuda_runtime.h>

// DynamicKVCache update: out = [concat(cache_k, key, dim=1), concat(cache_v, value, dim=1)]
// Shapes: cache [8, 4096, 32, 128] f32, new [8, 1, 32, 128] f32.
// H*D = 4096 floats per seq slot -> per-batch cache block = 4096*4096 floats,
// per-batch new block = 4096 floats. All boundaries 16B aligned -> float4 copy.

static constexpr long long CACHE_F4   = 4096LL * 4096 / 4;   // 4,194,304 float4 per batch (cache part)
static constexpr long long NEW_F4     = 4096LL / 4;          // 1,024 float4 per batch (appended slot)
static constexpr long long BATCH_F4   = CACHE_F4 + NEW_F4;   // 4,195,328 float4 per batch of output
static constexpr long long TENSOR_F4  = 8LL * BATCH_F4;      // per output tensor (k or v)
static constexpr int       THREADS    = 256;
static constexpr int       BLOCKS_X   = (int)(BATCH_F4 / THREADS); // 16388, exact

__global__ __launch_bounds__(THREADS)
void kvcache_concat_kernel(const float4* __restrict__ cache_k,
                           const float4* __restrict__ cache_v,
                           const float4* __restrict__ key,
                           const float4* __restrict__ value,
                           float4* __restrict__ out)
{
    const long long i = (long long)blockIdx.x * THREADS + threadIdx.x; // [0, BATCH_F4)
    const int b = blockIdx.y;        // batch
    const int t = blockIdx.z;        // 0 = k, 1 = v

    const float4* __restrict__ cache = t ? cache_v : cache_k;
    const float4* __restrict__ nw    = t ? value   : key;

    float4 val;
    if (i < CACHE_F4) {
        val = cache[(long long)b * CACHE_F4 + i];
    } else {
        val = nw[(long long)b * NEW_F4 + (i - CACHE_F4)];
    }
    out[(long long)t * TENSOR_F4 + (long long)b * BATCH_F4 + i] = val;
}

extern "C" void kernel_launch(void* const* d_in, const int* in_sizes, int n_in,
                              void* d_out, int out_size)
{
    const float4* cache_k = (const float4*)d_in[0];
    const float4* cache_v = (const float4*)d_in[1];
    const float4* key     = (const float4*)d_in[2];
    const float4* value   = (const float4*)d_in[3];
    float4* out = (float4*)d_out;

    dim3 grid(BLOCKS_X, 8, 2);
    kvcache_concat_kernel<<<grid, THREADS>>>(cache_k, cache_v, key, value, out);
}

// round 2
// speedup vs baseline: 1.0179x; 1.0179x over previous
#include <cuda_runtime.h>

// DynamicKVCache update: out = [concat(cache_k, key, dim=1), concat(cache_v, value, dim=1)]
// Shapes: cache [8, 4096, 32, 128] f32, new [8, 1, 32, 128] f32.
// Pure streaming copy, HBM-bound. Per-batch output = 4,195,328 float4
// = 4097 chunks of 1024 float4. Chunks 0..4095 come from the cache,
// chunk 4096 from the appended key/value -> uniform per-block branch.
// Each thread copies 4 independent float4 (MLP_p1=4) with .cs hints.

static constexpr long long CACHE_F4  = 4096LL * 4096 / 4;    // 4,194,304
static constexpr long long NEW_F4    = 4096LL / 4;           // 1,024
static constexpr long long BATCH_F4  = CACHE_F4 + NEW_F4;    // 4,195,328 = 4097 * 1024
static constexpr long long TENSOR_F4 = 8LL * BATCH_F4;
static constexpr int THREADS   = 256;
static constexpr int CHUNK_F4  = 1024;                       // float4 per block
static constexpr int BLOCKS_X  = (int)(BATCH_F4 / CHUNK_F4); // 4097, exact
static constexpr int CACHE_CHUNKS = (int)(CACHE_F4 / CHUNK_F4); // 4096

__global__ __launch_bounds__(THREADS)
void kvcache_concat_kernel(const float4* __restrict__ cache_k,
                           const float4* __restrict__ cache_v,
                           const float4* __restrict__ key,
                           const float4* __restrict__ value,
                           float4* __restrict__ out)
{
    const int chunk = blockIdx.x;    // [0, 4097)
    const int b     = blockIdx.y;    // batch
    const int t     = blockIdx.z;    // 0 = k, 1 = v

    const long long out_base = (long long)t * TENSOR_F4
                             + (long long)b * BATCH_F4
                             + (long long)chunk * CHUNK_F4;

    const float4* __restrict__ src;
    if (chunk < CACHE_CHUNKS) {
        const float4* __restrict__ cache = t ? cache_v : cache_k;
        src = cache + (long long)b * CACHE_F4 + (long long)chunk * CHUNK_F4;
    } else {
        const float4* __restrict__ nw = t ? value : key;
        src = nw + (long long)b * NEW_F4;
    }

    const int tid = threadIdx.x;
    // 4 independent 16B loads per thread, coalesced per warp, issued back-to-back.
    float4 v0 = __ldcs(src + tid);
    float4 v1 = __ldcs(src + tid + 256);
    float4 v2 = __ldcs(src + tid + 512);
    float4 v3 = __ldcs(src + tid + 768);
    __stcs(out + out_base + tid,       v0);
    __stcs(out + out_base + tid + 256, v1);
    __stcs(out + out_base + tid + 512, v2);
    __stcs(out + out_base + tid + 768, v3);
}

extern "C" void kernel_launch(void* const* d_in, const int* in_sizes, int n_in,
                              void* d_out, int out_size)
{
    const float4* cache_k = (const float4*)d_in[0];
    const float4* cache_v = (const float4*)d_in[1];
    const float4* key     = (const float4*)d_in[2];
    const float4* value   = (const float4*)d_in[3];
    float4* out = (float4*)d_out;

    dim3 grid(BLOCKS_X, 8, 2);
    kvcache_concat_kernel<<<grid, THREADS>>>(cache_k, cache_v, key, value, out);
}